// round 13
// baseline (speedup 1.0000x reference)
#include <cuda_runtime.h>
#include <cuda_fp16.h>
#include <mma.h>
#include <cstdint>

using namespace nvcuda;

// Problem constants (fixed-shape problem)
constexpr int NN   = 10000;         // nodes
constexpr int F    = 256;           // feature dim
constexpr int NF   = NN * F;        // elems per matrix
constexpr int EMAX = 320000;        // edges
constexpr int WSZ  = 65536;         // 256*256 per W
constexpr int SCAN_BLK   = 1024;
constexpr int SCAN_NBLK  = (NN + SCAN_BLK - 1) / SCAN_BLK;   // 10

// Scratch (__device__ globals; no allocation allowed)
__device__ __half g_h[3 * NF];      // H1|H2|H3 = fp16(X@W1..3)
__device__ __half g_s[2 * NF];      // s1, s2 intermediates (fp16)
__device__ __half g_xh[NF];         // fp16 X
__device__ __half g_wh[3 * WSZ];    // fp16 W1|W2|W3
__device__ int    g_cnt[NN];
__device__ int    g_rowptr[NN + 1];
__device__ int    g_off[NN];
__device__ int    g_bsum[SCAN_NBLK];
__device__ int2   g_epack[EMAX];    // CSR-ordered (src, __float_as_int(val))

// ---------------------------------------------------------------------------
// fp16 helpers
// ---------------------------------------------------------------------------
__device__ __forceinline__ float2 h2f(unsigned u) {
    __half2 h = *reinterpret_cast<__half2*>(&u);
    return __half22float2(h);
}
__device__ __forceinline__ unsigned f2h(float a, float b) {
    __half2 h = __floats2half2_rn(a, b);
    return *reinterpret_cast<unsigned*>(&h);
}

// cp.async helpers
__device__ __forceinline__ void cp_async16(uint32_t saddr, const void* gaddr, int src_sz) {
    asm volatile("cp.async.cg.shared.global [%0], [%1], 16, %2;"
                 :: "r"(saddr), "l"(gaddr), "r"(src_sz));
}
__device__ __forceinline__ void cp_commit() {
    asm volatile("cp.async.commit_group;");
}
template <int N>
__device__ __forceinline__ void cp_wait() {
    asm volatile("cp.async.wait_group %0;" :: "n"(N));
}

// ---------------------------------------------------------------------------
// Fused fp32->fp16 convert: X and W1..W3 in one launch (index-partitioned)
// ---------------------------------------------------------------------------
__global__ void conv_all_kernel(const float4* __restrict__ x,
                                const float4* __restrict__ W1,
                                const float4* __restrict__ W2,
                                const float4* __restrict__ W3,
                                uint2* __restrict__ xh, uint2* __restrict__ wh,
                                int n_x4)
{
    const int n_w4 = WSZ / 4;
    const int total = n_x4 + 3 * n_w4;
    int i = blockIdx.x * blockDim.x + threadIdx.x;
    int stride = gridDim.x * blockDim.x;
    for (; i < total; i += stride) {
        float4 v;
        uint2* out;
        if (i < n_x4) {
            v = __ldg(x + i);
            out = xh + i;
        } else {
            int j = i - n_x4;
            int which = j / n_w4;
            int k = j - which * n_w4;
            const float4* Wp = (which == 0) ? W1 : (which == 1) ? W2 : W3;
            v = __ldg(Wp + k);
            out = wh + (size_t)which * (WSZ / 4) + k;
        }
        uint2 o;
        o.x = f2h(v.x, v.y);
        o.y = f2h(v.z, v.w);
        *out = o;
    }
}

// ---------------------------------------------------------------------------
// CSR build: histogram -> 2-kernel coalesced scan -> scatter
// ---------------------------------------------------------------------------
__global__ void hist_kernel(const int* __restrict__ dst, int* cnt, int E) {
    int i0 = (blockIdx.x * blockDim.x + threadIdx.x) * 4;
#pragma unroll
    for (int j = 0; j < 4; j++) {
        int i = i0 + j;
        if (i < E) atomicAdd(&cnt[__ldg(dst + i)], 1);
    }
}

// k1: per-block reduction of cnt chunks -> bsum[b]
__global__ __launch_bounds__(SCAN_BLK) void scan_sum_kernel(
    const int* __restrict__ cnt, int* bsum, int n)
{
    int tid = threadIdx.x;
    int idx = blockIdx.x * SCAN_BLK + tid;
    int v = (idx < n) ? __ldg(cnt + idx) : 0;
#pragma unroll
    for (int d = 16; d > 0; d >>= 1)
        v += __shfl_down_sync(0xFFFFFFFFu, v, d);
    __shared__ int ws[32];
    int lane = tid & 31, w = tid >> 5;
    if (lane == 0) ws[w] = v;
    __syncthreads();
    if (w == 0) {
        int t = ws[lane];
#pragma unroll
        for (int d = 16; d > 0; d >>= 1)
            t += __shfl_down_sync(0xFFFFFFFFu, t, d);
        if (lane == 0) bsum[blockIdx.x] = t;
    }
}

// k2: block-local shuffle scan + cross-block prefix from bsum
__global__ __launch_bounds__(SCAN_BLK) void scan_fix_kernel(
    const int* __restrict__ cnt, const int* __restrict__ bsum,
    int* rowptr, int* off, int n)
{
    int tid = threadIdx.x;
    int b   = blockIdx.x;
    int idx = b * SCAN_BLK + tid;
    int lane = tid & 31, w = tid >> 5;

    int blockpre = 0;
    for (int i = 0; i < b; i++) blockpre += __ldg(bsum + i);

    int v = (idx < n) ? __ldg(cnt + idx) : 0;
    int cs = v;
#pragma unroll
    for (int d = 1; d < 32; d <<= 1) {
        int t = __shfl_up_sync(0xFFFFFFFFu, cs, d);
        if (lane >= d) cs += t;
    }
    __shared__ int ws[32];
    if (lane == 31) ws[w] = cs;
    __syncthreads();
    if (w == 0) {
        int t = ws[lane];
#pragma unroll
        for (int d = 1; d < 32; d <<= 1) {
            int u = __shfl_up_sync(0xFFFFFFFFu, t, d);
            if (lane >= d) t += u;
        }
        ws[lane] = t;
    }
    __syncthreads();
    int warppre = (w == 0) ? 0 : ws[w - 1];
    int excl = blockpre + warppre + cs - v;

    if (idx < n) {
        off[idx] = excl;
        rowptr[idx + 1] = excl + v;
    }
    if (idx == 0) rowptr[0] = 0;
}

__global__ void scatter_kernel(const int* __restrict__ src, const int* __restrict__ dst,
                               const float* __restrict__ vals,
                               int* off, int2* epack, int E) {
    int i0 = (blockIdx.x * blockDim.x + threadIdx.x) * 4;
    if (i0 + 3 < E) {
        int  d0 = __ldg(dst + i0),     d1 = __ldg(dst + i0 + 1);
        int  d2 = __ldg(dst + i0 + 2), d3 = __ldg(dst + i0 + 3);
        int  s0 = __ldg(src + i0),     s1 = __ldg(src + i0 + 1);
        int  s2 = __ldg(src + i0 + 2), s3 = __ldg(src + i0 + 3);
        float v0 = __ldg(vals + i0),     v1 = __ldg(vals + i0 + 1);
        float v2 = __ldg(vals + i0 + 2), v3 = __ldg(vals + i0 + 3);
        int p0 = atomicAdd(&off[d0], 1);
        int p1 = atomicAdd(&off[d1], 1);
        int p2 = atomicAdd(&off[d2], 1);
        int p3 = atomicAdd(&off[d3], 1);
        epack[p0] = make_int2(s0, __float_as_int(v0));
        epack[p1] = make_int2(s1, __float_as_int(v1));
        epack[p2] = make_int2(s2, __float_as_int(v2));
        epack[p3] = make_int2(s3, __float_as_int(v3));
    } else {
        for (int i = i0; i < E; i++) {
            int p = atomicAdd(&off[__ldg(dst + i)], 1);
            epack[p] = make_int2(__ldg(src + i), __float_as_int(__ldg(vals + i)));
        }
    }
}

// ---------------------------------------------------------------------------
// Tensor-core GEMM, cp.async double-buffered: H = fp16( Xh @ [W1|W2|W3]h ).
// wmma m16n16k16, fp32 acc. Block 256 = 8 warps (4m x 2n).
// Tile BM=128, BN=128, BK=64, 2 stages in dynamic SMEM.
// ---------------------------------------------------------------------------
constexpr int GBM = 128;
constexpr int GBN = 128;
constexpr int GBK = 64;
constexpr int APADH = 72;    // half-stride for As (144B, 16B multiple)
constexpr int BPADH = 136;   // half-stride for Bs (272B, 16B multiple)
constexpr int A_BYTES = GBM * APADH * 2;     // 18432
constexpr int B_BYTES = GBK * BPADH * 2;     // 17408
constexpr int STAGE_BYTES = A_BYTES + B_BYTES;
constexpr int GEMM_SMEM = 2 * STAGE_BYTES;   // 71680

__global__ __launch_bounds__(256) void gemm_wmma(
    const __half* __restrict__ xh,
    const __half* __restrict__ wh,
    __half* __restrict__ H, int M)
{
    extern __shared__ char smem[];

    const int n0 = blockIdx.x * GBN;       // over concat width 768
    const int m0 = blockIdx.y * GBM;
    const int which = n0 >> 8;
    const int wc0 = n0 & 255;
    const __half* Wp = wh + (size_t)which * WSZ;

    const int tid = threadIdx.x;
    const int wid = tid >> 5;
    const int warp_m = wid >> 1;           // 0..3 -> 32 rows each
    const int warp_n = wid & 1;            // 0..1 -> 64 cols each

    // Per-stage load: A tile 1024 uint4 + B tile 1024 uint4 (4 each/thread)
    auto load_stage = [&](int stage, int k0) {
        uint32_t sa = (uint32_t)__cvta_generic_to_shared(smem + stage * STAGE_BYTES);
        uint32_t sb = sa + A_BYTES;
#pragma unroll
        for (int l = 0; l < 4; l++) {
            int s   = tid + l * 256;       // 0..1023
            int row = s >> 3;              // 0..127
            int c4  = s & 7;               // uint4 col (8 halfs)
            int gm  = m0 + row;
            const void* g = xh + (size_t)gm * 256 + k0 + c4 * 8;
            cp_async16(sa + row * (APADH * 2) + c4 * 16, g, (gm < M) ? 16 : 0);
        }
#pragma unroll
        for (int l = 0; l < 4; l++) {
            int s  = tid + l * 256;
            int kr = s >> 4;               // 0..63
            int c4 = s & 15;               // uint4 col
            const void* g = Wp + (size_t)(k0 + kr) * 256 + wc0 + c4 * 8;
            cp_async16(sb + kr * (BPADH * 2) + c4 * 16, g, 16);
        }
        cp_commit();
    };

    wmma::fragment<wmma::accumulator, 16, 16, 16, float> cf[2][4];
#pragma unroll
    for (int i = 0; i < 2; i++)
#pragma unroll
        for (int j = 0; j < 4; j++) wmma::fill_fragment(cf[i][j], 0.f);

    load_stage(0, 0);

    constexpr int NSTEP = 256 / GBK;       // 4
#pragma unroll
    for (int s = 0; s < NSTEP; s++) {
        if (s + 1 < NSTEP) {
            load_stage((s + 1) & 1, (s + 1) * GBK);
            cp_wait<1>();
        } else {
            cp_wait<0>();
        }
        __syncthreads();

        const __half(*As)[APADH] =
            reinterpret_cast<const __half(*)[APADH]>(smem + (s & 1) * STAGE_BYTES);
        const __half(*Bs)[BPADH] =
            reinterpret_cast<const __half(*)[BPADH]>(smem + (s & 1) * STAGE_BYTES + A_BYTES);

#pragma unroll
        for (int kk = 0; kk < GBK; kk += 16) {
            wmma::fragment<wmma::matrix_a, 16, 16, 16, __half, wmma::row_major> af[2];
            wmma::fragment<wmma::matrix_b, 16, 16, 16, __half, wmma::row_major> bf[4];
#pragma unroll
            for (int mi = 0; mi < 2; mi++)
                wmma::load_matrix_sync(af[mi], &As[warp_m * 32 + mi * 16][kk], APADH);
#pragma unroll
            for (int ni = 0; ni < 4; ni++)
                wmma::load_matrix_sync(bf[ni], &Bs[kk][warp_n * 64 + ni * 16], BPADH);
#pragma unroll
            for (int mi = 0; mi < 2; mi++)
#pragma unroll
                for (int ni = 0; ni < 4; ni++)
                    wmma::mma_sync(cf[mi][ni], af[mi], bf[ni], cf[mi][ni]);
        }
        __syncthreads();   // buffer (s&1) free for reload at s+2
    }

    __half* Hout = H + (size_t)which * NF;
#pragma unroll
    for (int mi = 0; mi < 2; mi++) {
        int gm = m0 + warp_m * 32 + mi * 16;
        if (gm < M) {   // M % 16 == 0 -> whole fragment valid or out
#pragma unroll
            for (int ni = 0; ni < 4; ni++) {
                wmma::fragment<wmma::accumulator, 16, 16, 16, __half> ch;
#pragma unroll
                for (int e = 0; e < ch.num_elements; e++)
                    ch.x[e] = __float2half(cf[mi][ni].x[e]);
                wmma::store_matrix_sync(
                    Hout + (size_t)gm * 256 + wc0 + warp_n * 64 + ni * 16,
                    ch, 256, wmma::mem_row_major);
            }
        }
    }
}

// ---------------------------------------------------------------------------
// Horner SpMM pass: r = A @ gin (+ addin[row]); store fp16 (or relu(r/3) fp32).
// Warp per destination row. Lane owns halfs [8*lane, 8*lane+8) = one uint4.
// 4-edge batching (MLP=4 on the 512B row gathers). Packed int2 edge records.
// ---------------------------------------------------------------------------
__device__ __forceinline__ void acc_row(float* acc, uint4 r, float v) {
    float2 f0 = h2f(r.x), f1 = h2f(r.y), f2 = h2f(r.z), f3 = h2f(r.w);
    acc[0] = fmaf(v, f0.x, acc[0]); acc[1] = fmaf(v, f0.y, acc[1]);
    acc[2] = fmaf(v, f1.x, acc[2]); acc[3] = fmaf(v, f1.y, acc[3]);
    acc[4] = fmaf(v, f2.x, acc[4]); acc[5] = fmaf(v, f2.y, acc[5]);
    acc[6] = fmaf(v, f3.x, acc[6]); acc[7] = fmaf(v, f3.y, acc[7]);
}

template <bool ADD, bool FINAL>
__global__ __launch_bounds__(256) void spmm_pass(
    const int* __restrict__ rowptr, const int2* __restrict__ epack,
    const __half* __restrict__ gin,
    const __half* __restrict__ addin,
    __half* __restrict__ hout,
    float* __restrict__ fout, int n)
{
    int row = blockIdx.x * 8 + (threadIdx.x >> 5);
    if (row >= n) return;
    int lane = threadIdx.x & 31;
    int beg = rowptr[row], end = rowptr[row + 1];

    const uint4* base = reinterpret_cast<const uint4*>(gin);   // 32 uint4 per row

    float acc[8] = {0, 0, 0, 0, 0, 0, 0, 0};

    int e = beg;
    for (; e + 3 < end; e += 4) {
        int2 p0 = __ldg(epack + e),     p1 = __ldg(epack + e + 1);
        int2 p2 = __ldg(epack + e + 2), p3 = __ldg(epack + e + 3);
        uint4 r0 = __ldg(base + (size_t)p0.x * 32 + lane);
        uint4 r1 = __ldg(base + (size_t)p1.x * 32 + lane);
        uint4 r2 = __ldg(base + (size_t)p2.x * 32 + lane);
        uint4 r3 = __ldg(base + (size_t)p3.x * 32 + lane);
        acc_row(acc, r0, __int_as_float(p0.y));
        acc_row(acc, r1, __int_as_float(p1.y));
        acc_row(acc, r2, __int_as_float(p2.y));
        acc_row(acc, r3, __int_as_float(p3.y));
    }
    for (; e < end; e++) {
        int2 p = __ldg(epack + e);
        uint4 r = __ldg(base + (size_t)p.x * 32 + lane);
        acc_row(acc, r, __int_as_float(p.y));
    }

    if (ADD) {
        uint4 q = __ldg(reinterpret_cast<const uint4*>(addin) + (size_t)row * 32 + lane);
        float2 f0 = h2f(q.x), f1 = h2f(q.y), f2 = h2f(q.z), f3 = h2f(q.w);
        acc[0] += f0.x; acc[1] += f0.y; acc[2] += f1.x; acc[3] += f1.y;
        acc[4] += f2.x; acc[5] += f2.y; acc[6] += f3.x; acc[7] += f3.y;
    }

    if (FINAL) {
        const float inv3 = 1.0f / 3.0f;
        float4 r0, r1;
        r0.x = fmaxf(acc[0], 0.f) * inv3; r0.y = fmaxf(acc[1], 0.f) * inv3;
        r0.z = fmaxf(acc[2], 0.f) * inv3; r0.w = fmaxf(acc[3], 0.f) * inv3;
        r1.x = fmaxf(acc[4], 0.f) * inv3; r1.y = fmaxf(acc[5], 0.f) * inv3;
        r1.z = fmaxf(acc[6], 0.f) * inv3; r1.w = fmaxf(acc[7], 0.f) * inv3;
        float4* op = reinterpret_cast<float4*>(fout + (size_t)row * 256 + lane * 8);
        op[0] = r0; op[1] = r1;
    } else {
        uint4 o;
        o.x = f2h(acc[0], acc[1]);
        o.y = f2h(acc[2], acc[3]);
        o.z = f2h(acc[4], acc[5]);
        o.w = f2h(acc[6], acc[7]);
        *(reinterpret_cast<uint4*>(hout) + (size_t)row * 32 + lane) = o;
    }
}

// ---------------------------------------------------------------------------
// Launch — fork/join: (convert + GEMM) on side stream || CSR build on main.
// ---------------------------------------------------------------------------
static cudaStream_t g_s2 = nullptr;
static cudaEvent_t  g_evFork = nullptr, g_evJoin = nullptr;

extern "C" void kernel_launch(void* const* d_in, const int* in_sizes, int n_in,
                              void* d_out, int out_size)
{
    const float* x    = (const float*)d_in[0];
    const float* vals = (const float*)d_in[1];
    const float* W1   = (const float*)d_in[2];
    const float* W2   = (const float*)d_in[3];
    const float* W3   = (const float*)d_in[4];
    const int*   src  = (const int*)d_in[5];
    const int*   dst  = (const int*)d_in[6];

    const int M = in_sizes[0] / F;   // nodes
    const int E = in_sizes[1];       // edges

    __half* h;     cudaGetSymbolAddress((void**)&h,      g_h);
    __half* sbuf;  cudaGetSymbolAddress((void**)&sbuf,   g_s);
    __half* xh;    cudaGetSymbolAddress((void**)&xh,     g_xh);
    __half* wh;    cudaGetSymbolAddress((void**)&wh,     g_wh);
    int*   cnt;    cudaGetSymbolAddress((void**)&cnt,    g_cnt);
    int*   rowptr; cudaGetSymbolAddress((void**)&rowptr, g_rowptr);
    int*   off;    cudaGetSymbolAddress((void**)&off,    g_off);
    int*   bsum;   cudaGetSymbolAddress((void**)&bsum,   g_bsum);
    int2*  epack;  cudaGetSymbolAddress((void**)&epack,  g_epack);

    __half* h1 = h;
    __half* h2 = h + (size_t)NF;
    __half* h3 = h + (size_t)2 * NF;
    __half* s1 = sbuf;
    __half* s2 = sbuf + (size_t)NF;

    if (!g_s2) {
        cudaStreamCreateWithFlags(&g_s2, cudaStreamNonBlocking);
        cudaEventCreateWithFlags(&g_evFork, cudaEventDisableTiming);
        cudaEventCreateWithFlags(&g_evJoin, cudaEventDisableTiming);
        cudaFuncSetAttribute(gemm_wmma,
                             cudaFuncAttributeMaxDynamicSharedMemorySize, GEMM_SMEM);
    }

    // --- fork: convert + GEMM on side stream ---
    cudaEventRecord(g_evFork, 0);
    cudaStreamWaitEvent(g_s2, g_evFork, 0);
    conv_all_kernel<<<1024, 256, 0, g_s2>>>(
        (const float4*)x, (const float4*)W1, (const float4*)W2, (const float4*)W3,
        (uint2*)xh, (uint2*)wh, M * F / 4);
    {
        dim3 grid(768 / GBN, (M + GBM - 1) / GBM);
        gemm_wmma<<<grid, 256, GEMM_SMEM, g_s2>>>(xh, wh, h, M);
    }

    // --- CSR build on main stream (concurrent with GEMM) ---
    cudaMemsetAsync(cnt, 0, (size_t)M * sizeof(int), 0);
    hist_kernel<<<(E / 4 + 255) / 256, 256>>>(dst, cnt, E);
    {
        int nblk = (M + SCAN_BLK - 1) / SCAN_BLK;
        scan_sum_kernel<<<nblk, SCAN_BLK>>>(cnt, bsum, M);
        scan_fix_kernel<<<nblk, SCAN_BLK>>>(cnt, bsum, rowptr, off, M);
    }
    scatter_kernel<<<(E / 4 + 255) / 256, 256>>>(src, dst, vals, off, epack, E);

    // --- join ---
    cudaEventRecord(g_evJoin, g_s2);
    cudaStreamWaitEvent(0, g_evJoin, 0);

    // --- Horner SpMM chain: out = relu( A@(h1 + A@(h2 + A@h3)) / 3 ) ---
    const int rows_blocks = (M + 7) / 8;
    // s1 = A@h3 + h2
    spmm_pass<true, false><<<rows_blocks, 256>>>(rowptr, epack, h3, h2, s1, nullptr, M);
    // s2 = A@s1 + h1
    spmm_pass<true, false><<<rows_blocks, 256>>>(rowptr, epack, s1, h1, s2, nullptr, M);
    // out = relu(A@s2 / 3)
    spmm_pass<false, true><<<rows_blocks, 256>>>(rowptr, epack, s2, nullptr, nullptr,
                                                 (float*)d_out, M);
}

// round 14
// speedup vs baseline: 1.0151x; 1.0151x over previous
#include <cuda_runtime.h>
#include <cuda_fp16.h>
#include <mma.h>
#include <cstdint>

using namespace nvcuda;

// Problem constants (fixed-shape problem)
constexpr int NN   = 10000;         // nodes
constexpr int F    = 256;           // feature dim
constexpr int NF   = NN * F;        // elems per matrix
constexpr int EMAX = 320000;        // edges
constexpr int WSZ  = 65536;         // 256*256 per W
constexpr int SCAN_BLK   = 1024;
constexpr int SCAN_NBLK  = (NN + SCAN_BLK - 1) / SCAN_BLK;   // 10

// Scratch (__device__ globals; no allocation allowed)
__device__ __half g_h[3 * NF];      // H1|H2|H3 = fp16(X@W1..3)
__device__ __half g_s[2 * NF];      // s1, s2 intermediates (fp16)
__device__ __half g_xh[NF];         // fp16 X
__device__ __half g_wh[3 * WSZ];    // fp16 W1|W2|W3
__device__ int    g_cnt[NN];
__device__ int    g_rowptr[NN + 1];
__device__ int    g_off[NN];
__device__ int    g_bsum[SCAN_NBLK];
__device__ int2   g_epack[EMAX];    // CSR-ordered (src, __float_as_int(val))

// ---------------------------------------------------------------------------
// fp16 helpers
// ---------------------------------------------------------------------------
__device__ __forceinline__ float2 h2f(unsigned u) {
    __half2 h = *reinterpret_cast<__half2*>(&u);
    return __half22float2(h);
}
__device__ __forceinline__ unsigned f2h(float a, float b) {
    __half2 h = __floats2half2_rn(a, b);
    return *reinterpret_cast<unsigned*>(&h);
}

// ---------------------------------------------------------------------------
// Fused fp32->fp16 convert: X and W1..W3 in one launch (index-partitioned)
// ---------------------------------------------------------------------------
__global__ void conv_all_kernel(const float4* __restrict__ x,
                                const float4* __restrict__ W1,
                                const float4* __restrict__ W2,
                                const float4* __restrict__ W3,
                                uint2* __restrict__ xh, uint2* __restrict__ wh,
                                int n_x4)
{
    const int n_w4 = WSZ / 4;
    const int total = n_x4 + 3 * n_w4;
    int i = blockIdx.x * blockDim.x + threadIdx.x;
    int stride = gridDim.x * blockDim.x;
    for (; i < total; i += stride) {
        float4 v;
        uint2* out;
        if (i < n_x4) {
            v = __ldg(x + i);
            out = xh + i;
        } else {
            int j = i - n_x4;
            int which = j / n_w4;
            int k = j - which * n_w4;
            const float4* Wp = (which == 0) ? W1 : (which == 1) ? W2 : W3;
            v = __ldg(Wp + k);
            out = wh + (size_t)which * (WSZ / 4) + k;
        }
        uint2 o;
        o.x = f2h(v.x, v.y);
        o.y = f2h(v.z, v.w);
        *out = o;
    }
}

// ---------------------------------------------------------------------------
// CSR build: histogram -> 2-kernel coalesced scan -> scatter
// ---------------------------------------------------------------------------
__global__ void hist_kernel(const int* __restrict__ dst, int* cnt, int E) {
    int i0 = (blockIdx.x * blockDim.x + threadIdx.x) * 4;
#pragma unroll
    for (int j = 0; j < 4; j++) {
        int i = i0 + j;
        if (i < E) atomicAdd(&cnt[__ldg(dst + i)], 1);
    }
}

// k1: per-block reduction of cnt chunks -> bsum[b]
__global__ __launch_bounds__(SCAN_BLK) void scan_sum_kernel(
    const int* __restrict__ cnt, int* bsum, int n)
{
    int tid = threadIdx.x;
    int idx = blockIdx.x * SCAN_BLK + tid;
    int v = (idx < n) ? __ldg(cnt + idx) : 0;
#pragma unroll
    for (int d = 16; d > 0; d >>= 1)
        v += __shfl_down_sync(0xFFFFFFFFu, v, d);
    __shared__ int ws[32];
    int lane = tid & 31, w = tid >> 5;
    if (lane == 0) ws[w] = v;
    __syncthreads();
    if (w == 0) {
        int t = ws[lane];
#pragma unroll
        for (int d = 16; d > 0; d >>= 1)
            t += __shfl_down_sync(0xFFFFFFFFu, t, d);
        if (lane == 0) bsum[blockIdx.x] = t;
    }
}

// k2: block-local shuffle scan + cross-block prefix from bsum
__global__ __launch_bounds__(SCAN_BLK) void scan_fix_kernel(
    const int* __restrict__ cnt, const int* __restrict__ bsum,
    int* rowptr, int* off, int n)
{
    int tid = threadIdx.x;
    int b   = blockIdx.x;
    int idx = b * SCAN_BLK + tid;
    int lane = tid & 31, w = tid >> 5;

    int blockpre = 0;
    for (int i = 0; i < b; i++) blockpre += __ldg(bsum + i);

    int v = (idx < n) ? __ldg(cnt + idx) : 0;
    int cs = v;
#pragma unroll
    for (int d = 1; d < 32; d <<= 1) {
        int t = __shfl_up_sync(0xFFFFFFFFu, cs, d);
        if (lane >= d) cs += t;
    }
    __shared__ int ws[32];
    if (lane == 31) ws[w] = cs;
    __syncthreads();
    if (w == 0) {
        int t = ws[lane];
#pragma unroll
        for (int d = 1; d < 32; d <<= 1) {
            int u = __shfl_up_sync(0xFFFFFFFFu, t, d);
            if (lane >= d) t += u;
        }
        ws[lane] = t;
    }
    __syncthreads();
    int warppre = (w == 0) ? 0 : ws[w - 1];
    int excl = blockpre + warppre + cs - v;

    if (idx < n) {
        off[idx] = excl;
        rowptr[idx + 1] = excl + v;
    }
    if (idx == 0) rowptr[0] = 0;
}

__global__ void scatter_kernel(const int* __restrict__ src, const int* __restrict__ dst,
                               const float* __restrict__ vals,
                               int* off, int2* epack, int E) {
    int i0 = (blockIdx.x * blockDim.x + threadIdx.x) * 4;
    if (i0 + 3 < E) {
        int  d0 = __ldg(dst + i0),     d1 = __ldg(dst + i0 + 1);
        int  d2 = __ldg(dst + i0 + 2), d3 = __ldg(dst + i0 + 3);
        int  s0 = __ldg(src + i0),     s1 = __ldg(src + i0 + 1);
        int  s2 = __ldg(src + i0 + 2), s3 = __ldg(src + i0 + 3);
        float v0 = __ldg(vals + i0),     v1 = __ldg(vals + i0 + 1);
        float v2 = __ldg(vals + i0 + 2), v3 = __ldg(vals + i0 + 3);
        int p0 = atomicAdd(&off[d0], 1);
        int p1 = atomicAdd(&off[d1], 1);
        int p2 = atomicAdd(&off[d2], 1);
        int p3 = atomicAdd(&off[d3], 1);
        epack[p0] = make_int2(s0, __float_as_int(v0));
        epack[p1] = make_int2(s1, __float_as_int(v1));
        epack[p2] = make_int2(s2, __float_as_int(v2));
        epack[p3] = make_int2(s3, __float_as_int(v3));
    } else {
        for (int i = i0; i < E; i++) {
            int p = atomicAdd(&off[__ldg(dst + i)], 1);
            epack[p] = make_int2(__ldg(src + i), __float_as_int(__ldg(vals + i)));
        }
    }
}

// ---------------------------------------------------------------------------
// Tensor-core GEMM (fp16-staged, synchronous — R12 version, known-good):
// computes H columns [n0_base, n0_base + gridDim.x*GBN) of X @ [W1|W2|W3].
// wmma m16n16k16, fp32 acc. Block 256 = 8 warps (4m x 2n).
// ---------------------------------------------------------------------------
constexpr int GBM = 128;
constexpr int GBN = 128;
constexpr int GBK = 64;
constexpr int APADH = 72;    // half-stride for As (144B)
constexpr int BPADH = 136;   // half-stride for Bs (272B)

__global__ __launch_bounds__(256) void gemm_wmma(
    const __half* __restrict__ xh,
    const __half* __restrict__ wh,
    __half* __restrict__ H, int M, int n0_base)
{
    __shared__ alignas(16) __half As[GBM][APADH];
    __shared__ alignas(16) __half Bs[GBK][BPADH];

    const int n0 = n0_base + blockIdx.x * GBN;   // over concat width 768
    const int m0 = blockIdx.y * GBM;
    const int which = n0 >> 8;
    const int wc0 = n0 & 255;
    const __half* Wp = wh + (size_t)which * WSZ;

    const int tid = threadIdx.x;
    const int wid = tid >> 5;
    const int warp_m = wid >> 1;           // 0..3 -> 32 rows each
    const int warp_n = wid & 1;            // 0..1 -> 64 cols each

    wmma::fragment<wmma::accumulator, 16, 16, 16, float> cf[2][4];
#pragma unroll
    for (int i = 0; i < 2; i++)
#pragma unroll
        for (int j = 0; j < 4; j++) wmma::fill_fragment(cf[i][j], 0.f);

    for (int k0 = 0; k0 < 256; k0 += GBK) {
        // A tile: 128 rows x 64 halfs = 1024 uint4, 4 per thread
#pragma unroll
        for (int l = 0; l < 4; l++) {
            int s   = tid + l * 256;       // 0..1023
            int row = s >> 3;              // 0..127
            int c4  = s & 7;               // uint4 col (8 halfs)
            int gm  = m0 + row;
            uint4 v = make_uint4(0u, 0u, 0u, 0u);
            if (gm < M)
                v = *reinterpret_cast<const uint4*>(xh + (size_t)gm * 256 + k0 + c4 * 8);
            *reinterpret_cast<uint4*>(&As[row][c4 * 8]) = v;
        }
        // B tile: 64 k-rows x 128 halfs = 1024 uint4
#pragma unroll
        for (int l = 0; l < 4; l++) {
            int s  = tid + l * 256;
            int kr = s >> 4;               // 0..63
            int c4 = s & 15;               // uint4 col
            uint4 v = *reinterpret_cast<const uint4*>(
                Wp + (size_t)(k0 + kr) * 256 + wc0 + c4 * 8);
            *reinterpret_cast<uint4*>(&Bs[kr][c4 * 8]) = v;
        }
        __syncthreads();

#pragma unroll
        for (int kk = 0; kk < GBK; kk += 16) {
            wmma::fragment<wmma::matrix_a, 16, 16, 16, __half, wmma::row_major> af[2];
            wmma::fragment<wmma::matrix_b, 16, 16, 16, __half, wmma::row_major> bf[4];
#pragma unroll
            for (int mi = 0; mi < 2; mi++)
                wmma::load_matrix_sync(af[mi], &As[warp_m * 32 + mi * 16][kk], APADH);
#pragma unroll
            for (int ni = 0; ni < 4; ni++)
                wmma::load_matrix_sync(bf[ni], &Bs[kk][warp_n * 64 + ni * 16], BPADH);
#pragma unroll
            for (int mi = 0; mi < 2; mi++)
#pragma unroll
                for (int ni = 0; ni < 4; ni++)
                    wmma::mma_sync(cf[mi][ni], af[mi], bf[ni], cf[mi][ni]);
        }
        __syncthreads();
    }

    __half* Hout = H + (size_t)which * NF;
#pragma unroll
    for (int mi = 0; mi < 2; mi++) {
        int gm = m0 + warp_m * 32 + mi * 16;
        if (gm < M) {   // M % 16 == 0 -> whole fragment valid or out
#pragma unroll
            for (int ni = 0; ni < 4; ni++) {
                wmma::fragment<wmma::accumulator, 16, 16, 16, __half> ch;
#pragma unroll
                for (int e = 0; e < ch.num_elements; e++)
                    ch.x[e] = __float2half(cf[mi][ni].x[e]);
                wmma::store_matrix_sync(
                    Hout + (size_t)gm * 256 + wc0 + warp_n * 64 + ni * 16,
                    ch, 256, wmma::mem_row_major);
            }
        }
    }
}

// ---------------------------------------------------------------------------
// Horner SpMM pass: r = A @ gin (+ addin[row]); store fp16 (or relu(r/3) fp32).
// Warp per destination row. Lane owns halfs [8*lane, 8*lane+8) = one uint4.
// 4-edge batching (MLP=4 on the 512B row gathers). Packed int2 edge records.
// ---------------------------------------------------------------------------
__device__ __forceinline__ void acc_row(float* acc, uint4 r, float v) {
    float2 f0 = h2f(r.x), f1 = h2f(r.y), f2 = h2f(r.z), f3 = h2f(r.w);
    acc[0] = fmaf(v, f0.x, acc[0]); acc[1] = fmaf(v, f0.y, acc[1]);
    acc[2] = fmaf(v, f1.x, acc[2]); acc[3] = fmaf(v, f1.y, acc[3]);
    acc[4] = fmaf(v, f2.x, acc[4]); acc[5] = fmaf(v, f2.y, acc[5]);
    acc[6] = fmaf(v, f3.x, acc[6]); acc[7] = fmaf(v, f3.y, acc[7]);
}

template <bool ADD, bool FINAL>
__global__ __launch_bounds__(256) void spmm_pass(
    const int* __restrict__ rowptr, const int2* __restrict__ epack,
    const __half* __restrict__ gin,
    const __half* __restrict__ addin,
    __half* __restrict__ hout,
    float* __restrict__ fout, int n)
{
    int row = blockIdx.x * 8 + (threadIdx.x >> 5);
    if (row >= n) return;
    int lane = threadIdx.x & 31;
    int beg = rowptr[row], end = rowptr[row + 1];

    const uint4* base = reinterpret_cast<const uint4*>(gin);   // 32 uint4 per row

    float acc[8] = {0, 0, 0, 0, 0, 0, 0, 0};

    int e = beg;
    for (; e + 3 < end; e += 4) {
        int2 p0 = __ldg(epack + e),     p1 = __ldg(epack + e + 1);
        int2 p2 = __ldg(epack + e + 2), p3 = __ldg(epack + e + 3);
        uint4 r0 = __ldg(base + (size_t)p0.x * 32 + lane);
        uint4 r1 = __ldg(base + (size_t)p1.x * 32 + lane);
        uint4 r2 = __ldg(base + (size_t)p2.x * 32 + lane);
        uint4 r3 = __ldg(base + (size_t)p3.x * 32 + lane);
        acc_row(acc, r0, __int_as_float(p0.y));
        acc_row(acc, r1, __int_as_float(p1.y));
        acc_row(acc, r2, __int_as_float(p2.y));
        acc_row(acc, r3, __int_as_float(p3.y));
    }
    for (; e < end; e++) {
        int2 p = __ldg(epack + e);
        uint4 r = __ldg(base + (size_t)p.x * 32 + lane);
        acc_row(acc, r, __int_as_float(p.y));
    }

    if (ADD) {
        uint4 q = __ldg(reinterpret_cast<const uint4*>(addin) + (size_t)row * 32 + lane);
        float2 f0 = h2f(q.x), f1 = h2f(q.y), f2 = h2f(q.z), f3 = h2f(q.w);
        acc[0] += f0.x; acc[1] += f0.y; acc[2] += f1.x; acc[3] += f1.y;
        acc[4] += f2.x; acc[5] += f2.y; acc[6] += f3.x; acc[7] += f3.y;
    }

    if (FINAL) {
        const float inv3 = 1.0f / 3.0f;
        float4 r0, r1;
        r0.x = fmaxf(acc[0], 0.f) * inv3; r0.y = fmaxf(acc[1], 0.f) * inv3;
        r0.z = fmaxf(acc[2], 0.f) * inv3; r0.w = fmaxf(acc[3], 0.f) * inv3;
        r1.x = fmaxf(acc[4], 0.f) * inv3; r1.y = fmaxf(acc[5], 0.f) * inv3;
        r1.z = fmaxf(acc[6], 0.f) * inv3; r1.w = fmaxf(acc[7], 0.f) * inv3;
        float4* op = reinterpret_cast<float4*>(fout + (size_t)row * 256 + lane * 8);
        op[0] = r0; op[1] = r1;
    } else {
        uint4 o;
        o.x = f2h(acc[0], acc[1]);
        o.y = f2h(acc[2], acc[3]);
        o.z = f2h(acc[4], acc[5]);
        o.w = f2h(acc[6], acc[7]);
        *(reinterpret_cast<uint4*>(hout) + (size_t)row * 32 + lane) = o;
    }
}

// ---------------------------------------------------------------------------
// Launch — fork/join with split GEMM:
//   side stream: conv -> gemm(h2,h3) -> [evJ23] -> gemm(h1) -> [evJ1]
//   main stream: CSR build -> wait(evJ23) -> passA -> wait(evJ1) -> passB -> passC
// gemm(h1) overlaps passA (it's not needed until passB).
// ---------------------------------------------------------------------------
static cudaStream_t g_s2 = nullptr;
static cudaEvent_t  g_evFork = nullptr, g_evJ23 = nullptr, g_evJ1 = nullptr;

extern "C" void kernel_launch(void* const* d_in, const int* in_sizes, int n_in,
                              void* d_out, int out_size)
{
    const float* x    = (const float*)d_in[0];
    const float* vals = (const float*)d_in[1];
    const float* W1   = (const float*)d_in[2];
    const float* W2   = (const float*)d_in[3];
    const float* W3   = (const float*)d_in[4];
    const int*   src  = (const int*)d_in[5];
    const int*   dst  = (const int*)d_in[6];

    const int M = in_sizes[0] / F;   // nodes
    const int E = in_sizes[1];       // edges

    __half* h;     cudaGetSymbolAddress((void**)&h,      g_h);
    __half* sbuf;  cudaGetSymbolAddress((void**)&sbuf,   g_s);
    __half* xh;    cudaGetSymbolAddress((void**)&xh,     g_xh);
    __half* wh;    cudaGetSymbolAddress((void**)&wh,     g_wh);
    int*   cnt;    cudaGetSymbolAddress((void**)&cnt,    g_cnt);
    int*   rowptr; cudaGetSymbolAddress((void**)&rowptr, g_rowptr);
    int*   off;    cudaGetSymbolAddress((void**)&off,    g_off);
    int*   bsum;   cudaGetSymbolAddress((void**)&bsum,   g_bsum);
    int2*  epack;  cudaGetSymbolAddress((void**)&epack,  g_epack);

    __half* h1 = h;
    __half* h2 = h + (size_t)NF;
    __half* h3 = h + (size_t)2 * NF;
    __half* s1 = sbuf;
    __half* s2 = sbuf + (size_t)NF;

    if (!g_s2) {
        cudaStreamCreateWithFlags(&g_s2, cudaStreamNonBlocking);
        cudaEventCreateWithFlags(&g_evFork, cudaEventDisableTiming);
        cudaEventCreateWithFlags(&g_evJ23, cudaEventDisableTiming);
        cudaEventCreateWithFlags(&g_evJ1, cudaEventDisableTiming);
    }

    const int nmb = (M + GBM - 1) / GBM;

    // --- fork: convert + split GEMM on side stream ---
    cudaEventRecord(g_evFork, 0);
    cudaStreamWaitEvent(g_s2, g_evFork, 0);
    conv_all_kernel<<<1024, 256, 0, g_s2>>>(
        (const float4*)x, (const float4*)W1, (const float4*)W2, (const float4*)W3,
        (uint2*)xh, (uint2*)wh, M * F / 4);
    gemm_wmma<<<dim3(4, nmb), 256, 0, g_s2>>>(xh, wh, h, M, 256);  // h2, h3
    cudaEventRecord(g_evJ23, g_s2);
    gemm_wmma<<<dim3(2, nmb), 256, 0, g_s2>>>(xh, wh, h, M, 0);    // h1 (overlaps passA)
    cudaEventRecord(g_evJ1, g_s2);

    // --- CSR build on main stream (concurrent with GEMM) ---
    cudaMemsetAsync(cnt, 0, (size_t)M * sizeof(int), 0);
    hist_kernel<<<(E / 4 + 255) / 256, 256>>>(dst, cnt, E);
    {
        int nblk = (M + SCAN_BLK - 1) / SCAN_BLK;
        scan_sum_kernel<<<nblk, SCAN_BLK>>>(cnt, bsum, M);
        scan_fix_kernel<<<nblk, SCAN_BLK>>>(cnt, bsum, rowptr, off, M);
    }
    scatter_kernel<<<(E / 4 + 255) / 256, 256>>>(src, dst, vals, off, epack, E);

    // --- join 1: h2/h3 ready -> passA (gemm h1 still running concurrently) ---
    cudaStreamWaitEvent(0, g_evJ23, 0);
    const int rows_blocks = (M + 7) / 8;
    // s1 = A@h3 + h2
    spmm_pass<true, false><<<rows_blocks, 256>>>(rowptr, epack, h3, h2, s1, nullptr, M);

    // --- join 2: h1 ready -> passB ---
    cudaStreamWaitEvent(0, g_evJ1, 0);
    // s2 = A@s1 + h1
    spmm_pass<true, false><<<rows_blocks, 256>>>(rowptr, epack, s1, h1, s2, nullptr, M);
    // out = relu(A@s2 / 3)
    spmm_pass<false, true><<<rows_blocks, 256>>>(rowptr, epack, s2, nullptr, nullptr,
                                                 (float*)d_out, M);
}

// round 16
// speedup vs baseline: 1.0619x; 1.0461x over previous
#include <cuda_runtime.h>
#include <cuda_fp16.h>
#include <mma.h>
#include <cstdint>

using namespace nvcuda;

// Problem constants (fixed-shape problem)
constexpr int NN   = 10000;         // nodes
constexpr int F    = 256;           // feature dim
constexpr int NF   = NN * F;        // elems per matrix
constexpr int EMAX = 320000;        // edges
constexpr int WSZ  = 65536;         // 256*256 per W
constexpr int SCAN_BLK = 1024;

// Scratch (__device__ globals; no allocation allowed)
__device__ __half g_h[3 * NF];      // H1|H2|H3 = fp16(X@W1..3)
__device__ __half g_s[2 * NF];      // s1, s2 intermediates (fp16)
__device__ __half g_xh[NF];         // fp16 X
__device__ __half g_wh[3 * WSZ];    // fp16 W1|W2|W3
__device__ int    g_cnt[NN];
__device__ int    g_rowptr[NN + 1];
__device__ int    g_off[NN];
__device__ int2   g_epack[EMAX];    // CSR-ordered (src, __float_as_int(val))

// ---------------------------------------------------------------------------
// fp16 helpers
// ---------------------------------------------------------------------------
__device__ __forceinline__ float2 h2f(unsigned u) {
    __half2 h = *reinterpret_cast<__half2*>(&u);
    return __half22float2(h);
}
__device__ __forceinline__ unsigned f2h(float a, float b) {
    __half2 h = __floats2half2_rn(a, b);
    return *reinterpret_cast<unsigned*>(&h);
}

// ---------------------------------------------------------------------------
// Fused fp32->fp16 convert: X and W1..W3 in one launch (index-partitioned)
// ---------------------------------------------------------------------------
__global__ void conv_all_kernel(const float4* __restrict__ x,
                                const float4* __restrict__ W1,
                                const float4* __restrict__ W2,
                                const float4* __restrict__ W3,
                                uint2* __restrict__ xh, uint2* __restrict__ wh,
                                int n_x4)
{
    const int n_w4 = WSZ / 4;
    const int total = n_x4 + 3 * n_w4;
    int i = blockIdx.x * blockDim.x + threadIdx.x;
    int stride = gridDim.x * blockDim.x;
    for (; i < total; i += stride) {
        float4 v;
        uint2* out;
        if (i < n_x4) {
            v = __ldg(x + i);
            out = xh + i;
        } else {
            int j = i - n_x4;
            int which = j / n_w4;
            int k = j - which * n_w4;
            const float4* Wp = (which == 0) ? W1 : (which == 1) ? W2 : W3;
            v = __ldg(Wp + k);
            out = wh + (size_t)which * (WSZ / 4) + k;
        }
        uint2 o;
        o.x = f2h(v.x, v.y);
        o.y = f2h(v.z, v.w);
        *out = o;
    }
}

// ---------------------------------------------------------------------------
// CSR build: memset(cnt) -> histogram -> fused scan (read-only) -> scatter
// ---------------------------------------------------------------------------
__global__ void hist_kernel(const int* __restrict__ dst, int* cnt, int E) {
    int i0 = (blockIdx.x * blockDim.x + threadIdx.x) * 4;
#pragma unroll
    for (int j = 0; j < 4; j++) {
        int i = i0 + j;
        if (i < E) atomicAdd(&cnt[__ldg(dst + i)], 1);
    }
}

// Fused scan: each block b computes its prefix by cooperatively summing
// cnt[0 .. b*1024) (<= 9216 coalesced loads over 1024 threads), then does a
// block-local shuffle scan of its own 1024 elements. STRICTLY READ-ONLY on
// cnt — cross-block prefix reads other blocks' regions, so no block may
// mutate cnt (the R15 self-zero raced here).
__global__ __launch_bounds__(SCAN_BLK) void scan_kernel(
    const int* __restrict__ cnt, int* rowptr, int* off, int n)
{
    int tid = threadIdx.x;
    int b   = blockIdx.x;
    int idx = b * SCAN_BLK + tid;
    int lane = tid & 31, w = tid >> 5;
    __shared__ int ws[32];
    __shared__ int blockpre_s;

    // --- cross-block prefix: reduce cnt[0 .. b*1024) ---
    int pre = 0;
    for (int i = tid; i < b * SCAN_BLK; i += SCAN_BLK) pre += __ldg(cnt + i);
#pragma unroll
    for (int d = 16; d > 0; d >>= 1)
        pre += __shfl_down_sync(0xFFFFFFFFu, pre, d);
    if (lane == 0) ws[w] = pre;
    __syncthreads();
    if (tid == 0) {
        int t = 0;
#pragma unroll
        for (int i = 0; i < 32; i++) t += ws[i];
        blockpre_s = t;
    }
    __syncthreads();
    int blockpre = blockpre_s;
    __syncthreads();   // ws reused below

    // --- block-local scan of own 1024 elements ---
    int v = (idx < n) ? __ldg(cnt + idx) : 0;
    int cs = v;
#pragma unroll
    for (int d = 1; d < 32; d <<= 1) {
        int t = __shfl_up_sync(0xFFFFFFFFu, cs, d);
        if (lane >= d) cs += t;
    }
    if (lane == 31) ws[w] = cs;
    __syncthreads();
    if (w == 0) {
        int t = ws[lane];
#pragma unroll
        for (int d = 1; d < 32; d <<= 1) {
            int u = __shfl_up_sync(0xFFFFFFFFu, t, d);
            if (lane >= d) t += u;
        }
        ws[lane] = t;
    }
    __syncthreads();
    int warppre = (w == 0) ? 0 : ws[w - 1];
    int excl = blockpre + warppre + cs - v;

    if (idx < n) {
        off[idx] = excl;
        rowptr[idx + 1] = excl + v;
    }
    if (idx == 0) rowptr[0] = 0;
}

__global__ void scatter_kernel(const int* __restrict__ src, const int* __restrict__ dst,
                               const float* __restrict__ vals,
                               int* off, int2* epack, int E) {
    int i0 = (blockIdx.x * blockDim.x + threadIdx.x) * 4;
    if (i0 + 3 < E) {
        int  d0 = __ldg(dst + i0),     d1 = __ldg(dst + i0 + 1);
        int  d2 = __ldg(dst + i0 + 2), d3 = __ldg(dst + i0 + 3);
        int  s0 = __ldg(src + i0),     s1 = __ldg(src + i0 + 1);
        int  s2 = __ldg(src + i0 + 2), s3 = __ldg(src + i0 + 3);
        float v0 = __ldg(vals + i0),     v1 = __ldg(vals + i0 + 1);
        float v2 = __ldg(vals + i0 + 2), v3 = __ldg(vals + i0 + 3);
        int p0 = atomicAdd(&off[d0], 1);
        int p1 = atomicAdd(&off[d1], 1);
        int p2 = atomicAdd(&off[d2], 1);
        int p3 = atomicAdd(&off[d3], 1);
        epack[p0] = make_int2(s0, __float_as_int(v0));
        epack[p1] = make_int2(s1, __float_as_int(v1));
        epack[p2] = make_int2(s2, __float_as_int(v2));
        epack[p3] = make_int2(s3, __float_as_int(v3));
    } else {
        for (int i = i0; i < E; i++) {
            int p = atomicAdd(&off[__ldg(dst + i)], 1);
            epack[p] = make_int2(__ldg(src + i), __float_as_int(__ldg(vals + i)));
        }
    }
}

// ---------------------------------------------------------------------------
// Tensor-core GEMM (fp16-staged, synchronous — R12 version, known-good):
// H = fp16( Xh @ [W1|W2|W3]h ). wmma m16n16k16, fp32 acc.
// Block 256 = 8 warps (4m x 2n). Tile BM=128, BN=128, BK=64.
// Grid: (6, ceil(M/128)).
// ---------------------------------------------------------------------------
constexpr int GBM = 128;
constexpr int GBN = 128;
constexpr int GBK = 64;
constexpr int APADH = 72;    // half-stride for As (144B)
constexpr int BPADH = 136;   // half-stride for Bs (272B)

__global__ __launch_bounds__(256) void gemm_wmma(
    const __half* __restrict__ xh,
    const __half* __restrict__ wh,
    __half* __restrict__ H, int M)
{
    __shared__ alignas(16) __half As[GBM][APADH];
    __shared__ alignas(16) __half Bs[GBK][BPADH];

    const int n0 = blockIdx.x * GBN;       // over concat width 768
    const int m0 = blockIdx.y * GBM;
    const int which = n0 >> 8;
    const int wc0 = n0 & 255;
    const __half* Wp = wh + (size_t)which * WSZ;

    const int tid = threadIdx.x;
    const int wid = tid >> 5;
    const int warp_m = wid >> 1;           // 0..3 -> 32 rows each
    const int warp_n = wid & 1;            // 0..1 -> 64 cols each

    wmma::fragment<wmma::accumulator, 16, 16, 16, float> cf[2][4];
#pragma unroll
    for (int i = 0; i < 2; i++)
#pragma unroll
        for (int j = 0; j < 4; j++) wmma::fill_fragment(cf[i][j], 0.f);

    for (int k0 = 0; k0 < 256; k0 += GBK) {
        // A tile: 128 rows x 64 halfs = 1024 uint4, 4 per thread
#pragma unroll
        for (int l = 0; l < 4; l++) {
            int s   = tid + l * 256;       // 0..1023
            int row = s >> 3;              // 0..127
            int c4  = s & 7;               // uint4 col (8 halfs)
            int gm  = m0 + row;
            uint4 v = make_uint4(0u, 0u, 0u, 0u);
            if (gm < M)
                v = *reinterpret_cast<const uint4*>(xh + (size_t)gm * 256 + k0 + c4 * 8);
            *reinterpret_cast<uint4*>(&As[row][c4 * 8]) = v;
        }
        // B tile: 64 k-rows x 128 halfs = 1024 uint4
#pragma unroll
        for (int l = 0; l < 4; l++) {
            int s  = tid + l * 256;
            int kr = s >> 4;               // 0..63
            int c4 = s & 15;               // uint4 col
            uint4 v = *reinterpret_cast<const uint4*>(
                Wp + (size_t)(k0 + kr) * 256 + wc0 + c4 * 8);
            *reinterpret_cast<uint4*>(&Bs[kr][c4 * 8]) = v;
        }
        __syncthreads();

#pragma unroll
        for (int kk = 0; kk < GBK; kk += 16) {
            wmma::fragment<wmma::matrix_a, 16, 16, 16, __half, wmma::row_major> af[2];
            wmma::fragment<wmma::matrix_b, 16, 16, 16, __half, wmma::row_major> bf[4];
#pragma unroll
            for (int mi = 0; mi < 2; mi++)
                wmma::load_matrix_sync(af[mi], &As[warp_m * 32 + mi * 16][kk], APADH);
#pragma unroll
            for (int ni = 0; ni < 4; ni++)
                wmma::load_matrix_sync(bf[ni], &Bs[kk][warp_n * 64 + ni * 16], BPADH);
#pragma unroll
            for (int mi = 0; mi < 2; mi++)
#pragma unroll
                for (int ni = 0; ni < 4; ni++)
                    wmma::mma_sync(cf[mi][ni], af[mi], bf[ni], cf[mi][ni]);
        }
        __syncthreads();
    }

    __half* Hout = H + (size_t)which * NF;
#pragma unroll
    for (int mi = 0; mi < 2; mi++) {
        int gm = m0 + warp_m * 32 + mi * 16;
        if (gm < M) {   // M % 16 == 0 -> whole fragment valid or out
#pragma unroll
            for (int ni = 0; ni < 4; ni++) {
                wmma::fragment<wmma::accumulator, 16, 16, 16, __half> ch;
#pragma unroll
                for (int e = 0; e < ch.num_elements; e++)
                    ch.x[e] = __float2half(cf[mi][ni].x[e]);
                wmma::store_matrix_sync(
                    Hout + (size_t)gm * 256 + wc0 + warp_n * 64 + ni * 16,
                    ch, 256, wmma::mem_row_major);
            }
        }
    }
}

// ---------------------------------------------------------------------------
// Horner SpMM pass: r = A @ gin (+ addin[row]); store fp16 (or relu(r/3) fp32).
// Warp per destination row. Lane owns halfs [8*lane, 8*lane+8) = one uint4.
// 4-edge batching (MLP=4 on the 512B row gathers). Packed int2 edge records.
// ---------------------------------------------------------------------------
__device__ __forceinline__ void acc_row(float* acc, uint4 r, float v) {
    float2 f0 = h2f(r.x), f1 = h2f(r.y), f2 = h2f(r.z), f3 = h2f(r.w);
    acc[0] = fmaf(v, f0.x, acc[0]); acc[1] = fmaf(v, f0.y, acc[1]);
    acc[2] = fmaf(v, f1.x, acc[2]); acc[3] = fmaf(v, f1.y, acc[3]);
    acc[4] = fmaf(v, f2.x, acc[4]); acc[5] = fmaf(v, f2.y, acc[5]);
    acc[6] = fmaf(v, f3.x, acc[6]); acc[7] = fmaf(v, f3.y, acc[7]);
}

template <bool ADD, bool FINAL>
__global__ __launch_bounds__(256) void spmm_pass(
    const int* __restrict__ rowptr, const int2* __restrict__ epack,
    const __half* __restrict__ gin,
    const __half* __restrict__ addin,
    __half* __restrict__ hout,
    float* __restrict__ fout, int n)
{
    int row = blockIdx.x * 8 + (threadIdx.x >> 5);
    if (row >= n) return;
    int lane = threadIdx.x & 31;
    int beg = rowptr[row], end = rowptr[row + 1];

    const uint4* base = reinterpret_cast<const uint4*>(gin);   // 32 uint4 per row

    float acc[8] = {0, 0, 0, 0, 0, 0, 0, 0};

    int e = beg;
    for (; e + 3 < end; e += 4) {
        int2 p0 = __ldg(epack + e),     p1 = __ldg(epack + e + 1);
        int2 p2 = __ldg(epack + e + 2), p3 = __ldg(epack + e + 3);
        uint4 r0 = __ldg(base + (size_t)p0.x * 32 + lane);
        uint4 r1 = __ldg(base + (size_t)p1.x * 32 + lane);
        uint4 r2 = __ldg(base + (size_t)p2.x * 32 + lane);
        uint4 r3 = __ldg(base + (size_t)p3.x * 32 + lane);
        acc_row(acc, r0, __int_as_float(p0.y));
        acc_row(acc, r1, __int_as_float(p1.y));
        acc_row(acc, r2, __int_as_float(p2.y));
        acc_row(acc, r3, __int_as_float(p3.y));
    }
    for (; e < end; e++) {
        int2 p = __ldg(epack + e);
        uint4 r = __ldg(base + (size_t)p.x * 32 + lane);
        acc_row(acc, r, __int_as_float(p.y));
    }

    if (ADD) {
        uint4 q = __ldg(reinterpret_cast<const uint4*>(addin) + (size_t)row * 32 + lane);
        float2 f0 = h2f(q.x), f1 = h2f(q.y), f2 = h2f(q.z), f3 = h2f(q.w);
        acc[0] += f0.x; acc[1] += f0.y; acc[2] += f1.x; acc[3] += f1.y;
        acc[4] += f2.x; acc[5] += f2.y; acc[6] += f3.x; acc[7] += f3.y;
    }

    if (FINAL) {
        const float inv3 = 1.0f / 3.0f;
        float4 r0, r1;
        r0.x = fmaxf(acc[0], 0.f) * inv3; r0.y = fmaxf(acc[1], 0.f) * inv3;
        r0.z = fmaxf(acc[2], 0.f) * inv3; r0.w = fmaxf(acc[3], 0.f) * inv3;
        r1.x = fmaxf(acc[4], 0.f) * inv3; r1.y = fmaxf(acc[5], 0.f) * inv3;
        r1.z = fmaxf(acc[6], 0.f) * inv3; r1.w = fmaxf(acc[7], 0.f) * inv3;
        float4* op = reinterpret_cast<float4*>(fout + (size_t)row * 256 + lane * 8);
        op[0] = r0; op[1] = r1;
    } else {
        uint4 o;
        o.x = f2h(acc[0], acc[1]);
        o.y = f2h(acc[2], acc[3]);
        o.z = f2h(acc[4], acc[5]);
        o.w = f2h(acc[6], acc[7]);
        *(reinterpret_cast<uint4*>(hout) + (size_t)row * 32 + lane) = o;
    }
}

// ---------------------------------------------------------------------------
// Launch — fork/join: (convert + GEMM) on side stream || CSR build on main.
// ---------------------------------------------------------------------------
static cudaStream_t g_s2 = nullptr;
static cudaEvent_t  g_evFork = nullptr, g_evJoin = nullptr;

extern "C" void kernel_launch(void* const* d_in, const int* in_sizes, int n_in,
                              void* d_out, int out_size)
{
    const float* x    = (const float*)d_in[0];
    const float* vals = (const float*)d_in[1];
    const float* W1   = (const float*)d_in[2];
    const float* W2   = (const float*)d_in[3];
    const float* W3   = (const float*)d_in[4];
    const int*   src  = (const int*)d_in[5];
    const int*   dst  = (const int*)d_in[6];

    const int M = in_sizes[0] / F;   // nodes
    const int E = in_sizes[1];       // edges

    __half* h;     cudaGetSymbolAddress((void**)&h,      g_h);
    __half* sbuf;  cudaGetSymbolAddress((void**)&sbuf,   g_s);
    __half* xh;    cudaGetSymbolAddress((void**)&xh,     g_xh);
    __half* wh;    cudaGetSymbolAddress((void**)&wh,     g_wh);
    int*   cnt;    cudaGetSymbolAddress((void**)&cnt,    g_cnt);
    int*   rowptr; cudaGetSymbolAddress((void**)&rowptr, g_rowptr);
    int*   off;    cudaGetSymbolAddress((void**)&off,    g_off);
    int2*  epack;  cudaGetSymbolAddress((void**)&epack,  g_epack);

    __half* h1 = h;
    __half* h2 = h + (size_t)NF;
    __half* h3 = h + (size_t)2 * NF;
    __half* s1 = sbuf;
    __half* s2 = sbuf + (size_t)NF;

    if (!g_s2) {
        cudaStreamCreateWithFlags(&g_s2, cudaStreamNonBlocking);
        cudaEventCreateWithFlags(&g_evFork, cudaEventDisableTiming);
        cudaEventCreateWithFlags(&g_evJoin, cudaEventDisableTiming);
    }

    // --- fork: convert + GEMM on side stream ---
    cudaEventRecord(g_evFork, 0);
    cudaStreamWaitEvent(g_s2, g_evFork, 0);
    conv_all_kernel<<<1024, 256, 0, g_s2>>>(
        (const float4*)x, (const float4*)W1, (const float4*)W2, (const float4*)W3,
        (uint2*)xh, (uint2*)wh, M * F / 4);
    {
        dim3 grid(768 / GBN, (M + GBM - 1) / GBM);
        gemm_wmma<<<grid, 256, 0, g_s2>>>(xh, wh, h, M);
    }

    // --- CSR build on main stream (concurrent with GEMM) ---
    cudaMemsetAsync(cnt, 0, (size_t)M * sizeof(int), 0);
    hist_kernel<<<(E / 4 + 255) / 256, 256>>>(dst, cnt, E);
    {
        int nblk = (M + SCAN_BLK - 1) / SCAN_BLK;
        scan_kernel<<<nblk, SCAN_BLK>>>(cnt, rowptr, off, M);
    }
    scatter_kernel<<<(E / 4 + 255) / 256, 256>>>(src, dst, vals, off, epack, E);

    // --- join ---
    cudaEventRecord(g_evJoin, g_s2);
    cudaStreamWaitEvent(0, g_evJoin, 0);

    // --- Horner SpMM chain: out = relu( A@(h1 + A@(h2 + A@h3)) / 3 ) ---
    const int rows_blocks = (M + 7) / 8;
    // s1 = A@h3 + h2
    spmm_pass<true, false><<<rows_blocks, 256>>>(rowptr, epack, h3, h2, s1, nullptr, M);
    // s2 = A@s1 + h1
    spmm_pass<true, false><<<rows_blocks, 256>>>(rowptr, epack, s1, h1, s2, nullptr, M);
    // out = relu(A@s2 / 3)
    spmm_pass<false, true><<<rows_blocks, 256>>>(rowptr, epack, s2, nullptr, nullptr,
                                                 (float*)d_out, M);
}